// round 16
// baseline (speedup 1.0000x reference)
#include <cuda_runtime.h>
#include <math.h>

// RNNDecoder persistent CTA kernel, v3 (fp32, proven numerics).
// R6 (MT=32) = 17.06 ms used only 128/148 SMs. v3: MT=28 -> 147 CTAs, one
// wave, per-SM work x28/32. Per-element arithmetic is bit-identical to R6
// (same k-order FFMA2 accumulation, same tanhf, same feedback), so rel_err
// is unchanged at 4.6e-4. Last CTA is ragged: z-rows clamped (pads compute a
// duplicate of row B-1; stores guarded).

#define LAT 128
#define HID 1024
#define OBS 64
#define MT  28          // batch rows per CTA
#define NP  14          // m-pairs per CTA (MT/2)
#define NT  512
#define MS  28          // m-stride (floats); 112B rows, 16B aligned

typedef unsigned long long u64;

// Transposed weights (filled once per launch; __device__ globals = scratch).
__device__ float g_WhhT [HID * HID];   // [k][n]
__device__ float g_WihT [OBS * HID];   // [k][n]
__device__ float g_Wl2hT[LAT * HID];   // [k][n]
__device__ float g_WhoT [HID * OBS];   // [j][o]

__device__ __forceinline__ u64 dup2(float w) {
    u64 r; unsigned u = __float_as_uint(w);
    asm("mov.b64 %0, {%1, %1};" : "=l"(r) : "r"(u));
    return r;
}
__device__ __forceinline__ void fma2(u64 &acc, u64 a, u64 b) {
    asm("fma.rn.f32x2 %0, %1, %2, %0;" : "+l"(acc) : "l"(a), "l"(b));
}
__device__ __forceinline__ float2 unpk(u64 v) {
    unsigned lo, hi;
    asm("mov.b64 {%0, %1}, %2;" : "=r"(lo), "=r"(hi) : "l"(v));
    return make_float2(__uint_as_float(lo), __uint_as_float(hi));
}
__device__ __forceinline__ u64 pk2(float x, float y) {
    u64 r;
    asm("mov.b64 %0, {%1, %2};" : "=l"(r) : "r"(__float_as_uint(x)), "r"(__float_as_uint(y)));
    return r;
}

// ---- 32x32-tiled transpose: dst[C][R] = src[R][C]^T (dims % 32 == 0) ----
__global__ void transpose_kernel(const float* __restrict__ src,
                                 float* __restrict__ dst, int R, int C)
{
    __shared__ float t[32][33];
    int c0 = blockIdx.x * 32, r0 = blockIdx.y * 32;
    int x = threadIdx.x, y = threadIdx.y;
    #pragma unroll
    for (int i = y; i < 32; i += 8)
        t[i][x] = src[(size_t)(r0 + i) * C + c0 + x];
    __syncthreads();
    #pragma unroll
    for (int i = y; i < 32; i += 8)
        dst[(size_t)(c0 + i) * R + r0 + x] = t[x][i];
}

// Accumulate 2 consecutive output columns (n0, n0+1) over K against the
// k-major activation tile ks[K][MS]. wt points at transposed weights + n0
// (element (k, n0) at wt[k*HID]). Warp lanes -> 256B coalesced weight reads.
template<int K>
__device__ __forceinline__ void dotT(const float* __restrict__ wt,
                                     const float* __restrict__ ks,
                                     u64* __restrict__ a0, u64* __restrict__ a1)
{
    float2 cur0 = *(const float2*)(wt + 0 * HID);
    float2 cur1 = *(const float2*)(wt + 1 * HID);
    float2 cur2 = *(const float2*)(wt + 2 * HID);
    float2 cur3 = *(const float2*)(wt + 3 * HID);
    #pragma unroll 1
    for (int k = 0; k < K; k += 4) {
        int kn = (k + 4 < K) ? (k + 4) : 0;            // wrap-clamped prefetch
        float2 nx0 = *(const float2*)(wt + (kn + 0) * HID);
        float2 nx1 = *(const float2*)(wt + (kn + 1) * HID);
        float2 nx2 = *(const float2*)(wt + (kn + 2) * HID);
        float2 nx3 = *(const float2*)(wt + (kn + 3) * HID);
        #pragma unroll
        for (int kk = 0; kk < 4; ++kk) {
            float2 w = (kk == 0) ? cur0 : (kk == 1) ? cur1 : (kk == 2) ? cur2 : cur3;
            u64 d0 = dup2(w.x), d1 = dup2(w.y);
            const ulonglong2* hp = (const ulonglong2*)(ks + (k + kk) * MS);
            #pragma unroll
            for (int q = 0; q < 7; ++q) {              // 14 pairs, broadcast LDS.128
                ulonglong2 hv = hp[q];
                fma2(a0[2*q    ], hv.x, d0);
                fma2(a0[2*q + 1], hv.y, d0);
                fma2(a1[2*q    ], hv.x, d1);
                fma2(a1[2*q + 1], hv.y, d1);
            }
        }
        cur0 = nx0; cur1 = nx1; cur2 = nx2; cur3 = nx3;
    }
}

__global__ void __launch_bounds__(NT, 1)
rnn_decoder_kernel(const float* __restrict__ z,
                   const float* __restrict__ b_l2h,
                   const float* __restrict__ b_ih,
                   const float* __restrict__ b_hh,
                   const float* __restrict__ b_ho,
                   float* __restrict__ out, int T, int B)
{
    extern __shared__ float smem[];
    float* h_s  = smem;                   // [HID][MS]  hidden state, k-major
    float* zx_s = h_s + HID * MS;         // [LAT][MS]  z, then x[OBS][MS]
    float* bs_s = zx_s + LAT * MS;        // [HID]      b_ih + b_hh
    float* bo_s = bs_s + HID;             // [OBS]      b_ho

    const int tid = threadIdx.x;
    const int b0  = blockIdx.x * MT;
    const int n0  = 2 * tid;              // this thread's 2 hidden columns

    for (int n = tid; n < HID; n += NT) bs_s[n] = b_ih[n] + b_hh[n];
    if (tid < OBS) bo_s[tid] = b_ho[tid];
    for (int idx = tid; idx < MT * LAT; idx += NT) {
        int m = idx >> 7;                 // / LAT
        int k = idx & (LAT - 1);
        int gr = b0 + m; if (gr >= B) gr = B - 1;     // clamp ragged tail
        zx_s[k * MS + m] = z[(size_t)gr * LAT + k];
    }
    __syncthreads();

    // ---- h0 = z @ W_l2h^T + b_l2h (no tanh) ----
    {
        u64 a0[NP], a1[NP];
        u64 bv0 = dup2(b_l2h[n0]), bv1 = dup2(b_l2h[n0 + 1]);
        #pragma unroll
        for (int p = 0; p < NP; ++p) { a0[p] = bv0; a1[p] = bv1; }
        dotT<LAT>(g_Wl2hT + n0, zx_s, a0, a1);
        __syncthreads();                  // reads of z done before zx_s reuse
        float* r0 = h_s + n0 * MS;
        float* r1 = r0 + MS;
        #pragma unroll
        for (int p = 0; p < NP; ++p) {
            float2 v0 = unpk(a0[p]); float2 v1 = unpk(a1[p]);
            r0[2*p] = v0.x; r0[2*p + 1] = v0.y;
            r1[2*p] = v1.x; r1[2*p + 1] = v1.y;
        }
        for (int idx = tid; idx < OBS * MT; idx += NT) {   // x0 = 0
            int o = idx / MT, m = idx % MT;
            zx_s[o * MS + m] = 0.0f;
        }
        __syncthreads();
    }

    const int o    = tid & (OBS - 1);     // phase-2 output column
    const int g    = tid >> 6;            // pair-group 0..7
    const int p0   = g;
    const bool has2 = (g + 8 < NP);       // g < 6
    const int p1   = has2 ? g + 8 : g;    // valid pair (dup if !has2)

    for (int t = 0; t < T; ++t) {
        // ---- phase 1: h = tanh(x W_ih^T + h W_hh^T + bias) ----
        u64 a0[NP], a1[NP];
        u64 bv0 = dup2(bs_s[n0]), bv1 = dup2(bs_s[n0 + 1]);
        #pragma unroll
        for (int p = 0; p < NP; ++p) { a0[p] = bv0; a1[p] = bv1; }
        dotT<HID>(g_WhhT + n0, h_s,  a0, a1);
        dotT<OBS>(g_WihT + n0, zx_s, a0, a1);
        __syncthreads();                  // all reads of old h / old x done
        {
            float* r0 = h_s + n0 * MS;
            float* r1 = r0 + MS;
            #pragma unroll
            for (int p = 0; p < NP; ++p) {
                float2 v0 = unpk(a0[p]); float2 v1 = unpk(a1[p]);
                r0[2*p] = tanhf(v0.x); r0[2*p + 1] = tanhf(v0.y);
                r1[2*p] = tanhf(v1.x); r1[2*p + 1] = tanhf(v1.y);
            }
        }
        __syncthreads();                  // new h visible

        // ---- phase 2: y = h W_ho^T + b_ho; emit; x <- y ----
        {
            u64 y0 = dup2(bo_s[o]), y1 = y0;
            const float* wp = g_WhoT + o;             // stride OBS per j (coalesced)
            float w0c = wp[0*OBS], w1c = wp[1*OBS], w2c = wp[2*OBS], w3c = wp[3*OBS];
            #pragma unroll 1
            for (int j = 0; j < HID; j += 4) {
                int jn = (j + 4 < HID) ? (j + 4) : 0;
                float nw0 = wp[(jn+0)*OBS], nw1 = wp[(jn+1)*OBS];
                float nw2 = wp[(jn+2)*OBS], nw3 = wp[(jn+3)*OBS];
                #pragma unroll
                for (int kk = 0; kk < 4; ++kk) {
                    float s = (kk==0)?w0c:(kk==1)?w1c:(kk==2)?w2c:w3c;
                    u64 d = dup2(s);
                    const u64* hr = (const u64*)(h_s + (j + kk) * MS);
                    fma2(y0, hr[p0], d);
                    fma2(y1, hr[p1], d);
                }
                w0c = nw0; w1c = nw1; w2c = nw2; w3c = nw3;
            }
            const size_t st = (size_t)T * OBS;
            {   // pair p0
                float2 v = unpk(y0);
                int m = 2 * p0;
                if (b0 + m < B) {
                    size_t base = (size_t)(b0 + m) * st + (size_t)t * OBS + o;
                    out[base] = v.x;
                    if (b0 + m + 1 < B) out[base + st] = v.y;
                }
                *(u64*)(zx_s + o * MS + m) = pk2(v.x, v.y);
            }
            if (has2) {   // pair p1
                float2 v = unpk(y1);
                int m = 2 * p1;
                if (b0 + m < B) {
                    size_t base = (size_t)(b0 + m) * st + (size_t)t * OBS + o;
                    out[base] = v.x;
                    if (b0 + m + 1 < B) out[base + st] = v.y;
                }
                *(u64*)(zx_s + o * MS + m) = pk2(v.x, v.y);
            }
        }
        __syncthreads();                  // x visible before next step
    }
}

extern "C" void kernel_launch(void* const* d_in, const int* in_sizes, int n_in,
                              void* d_out, int out_size)
{
    const float* z     = (const float*)d_in[0];
    const float* W_l2h = (const float*)d_in[1];
    const float* b_l2h = (const float*)d_in[2];
    const float* W_ih  = (const float*)d_in[3];
    const float* b_ih  = (const float*)d_in[4];
    const float* W_hh  = (const float*)d_in[5];
    const float* b_hh  = (const float*)d_in[6];
    const float* W_ho  = (const float*)d_in[7];
    const float* b_ho  = (const float*)d_in[8];
    float* out = (float*)d_out;

    int B = in_sizes[0] / LAT;              // 4096
    int T = out_size / (B * OBS);           // 70

    float *dWhhT, *dWihT, *dWl2hT, *dWhoT;
    cudaGetSymbolAddress((void**)&dWhhT,  g_WhhT);
    cudaGetSymbolAddress((void**)&dWihT,  g_WihT);
    cudaGetSymbolAddress((void**)&dWl2hT, g_Wl2hT);
    cudaGetSymbolAddress((void**)&dWhoT,  g_WhoT);

    dim3 tb(32, 8);
    transpose_kernel<<<dim3(LAT/32, HID/32), tb>>>(W_l2h, dWl2hT, HID, LAT);
    transpose_kernel<<<dim3(OBS/32, HID/32), tb>>>(W_ih,  dWihT,  HID, OBS);
    transpose_kernel<<<dim3(HID/32, HID/32), tb>>>(W_hh,  dWhhT,  HID, HID);
    transpose_kernel<<<dim3(HID/32, OBS/32), tb>>>(W_ho,  dWhoT,  OBS, HID);

    int smem_bytes = (HID * MS + LAT * MS + HID + OBS) * (int)sizeof(float); // 133,376 B
    cudaFuncSetAttribute(rnn_decoder_kernel,
                         cudaFuncAttributeMaxDynamicSharedMemorySize, smem_bytes);

    int grid = (B + MT - 1) / MT;           // 147 CTAs <= 148 SMs, one wave
    rnn_decoder_kernel<<<grid, NT, smem_bytes>>>(
        z, b_l2h, b_ih, b_hh, b_ho, out, T, B);
}

// round 17
// speedup vs baseline: 1.2022x; 1.2022x over previous
#include <cuda_runtime.h>
#include <math.h>

// RNNDecoder persistent CTA kernel, v4 (fp32, fused recurrence).
// R15 analysis: FFMA2 is RF-bank-bound at rt=3 -> kernel is at ~94% of the
// fp32 roofline. Only lever left: fewer FMA2s. Exact fusion
//   x_{t+1} = h_{t+1} Who^T + b_ho  =>
//   h_{t+1} = tanh(h_t (Whh + Wih Who)^T + b_ih + b_hh + Wih b_ho)  (t>=1)
// (Wf, b1 built in fp64). t=0 (x0=0) stays bit-identical to R15. h history
// is stored per step; ALL outputs come from one parallel GEMM at the end.

#define LAT 128
#define HID 1024
#define OBS 64
#define MT  28          // batch rows per CTA
#define NP  14          // m-pairs per CTA
#define NT  512
#define MS  28          // m-stride (floats) in k-major smem tiles
#define TMAX 70
#define BMAX 4096

typedef unsigned long long u64;

// ---- device scratch (sanctioned: __device__ globals) ----
__device__ float g_WfT  [HID * HID];   // fused (Whh + Wih Who), transposed [k][n]
__device__ float g_WhhT [HID * HID];   // [k][n]  (t=0 step)
__device__ float g_Wl2hT[LAT * HID];   // [k][n]
__device__ float g_WhoT [HID * OBS];   // [j][o]
__device__ float g_b1   [HID];         // b_ih + b_hh + Wih b_ho (fp64-built)
__device__ float g_Hist [(size_t)TMAX * BMAX * HID];   // h_{t+1} at slot t

__device__ __forceinline__ u64 dup2(float w) {
    u64 r; unsigned u = __float_as_uint(w);
    asm("mov.b64 %0, {%1, %1};" : "=l"(r) : "r"(u));
    return r;
}
__device__ __forceinline__ void fma2(u64 &acc, u64 a, u64 b) {
    asm("fma.rn.f32x2 %0, %1, %2, %0;" : "+l"(acc) : "l"(a), "l"(b));
}
__device__ __forceinline__ float2 unpk(u64 v) {
    unsigned lo, hi;
    asm("mov.b64 {%0, %1}, %2;" : "=r"(lo), "=r"(hi) : "l"(v));
    return make_float2(__uint_as_float(lo), __uint_as_float(hi));
}
__device__ __forceinline__ u64 pk2(float x, float y) {
    u64 r;
    asm("mov.b64 %0, {%1, %2};" : "=l"(r) : "r"(__float_as_uint(x)), "r"(__float_as_uint(y)));
    return r;
}

// ---- 32x32-tiled transpose: dst[C][R] = src[R][C]^T ----
__global__ void transpose_kernel(const float* __restrict__ src,
                                 float* __restrict__ dst, int R, int C)
{
    __shared__ float t[32][33];
    int c0 = blockIdx.x * 32, r0 = blockIdx.y * 32;
    int x = threadIdx.x, y = threadIdx.y;
    #pragma unroll
    for (int i = y; i < 32; i += 8)
        t[i][x] = src[(size_t)(r0 + i) * C + c0 + x];
    __syncthreads();
    #pragma unroll
    for (int i = y; i < 32; i += 8)
        dst[(size_t)(c0 + i) * R + r0 + x] = t[x][i];
}

// ---- WfT[k][n] = Whh[n][k] + sum_o Wih[n][o] Who[o][k]  (fp64 accumulate) ----
__global__ void fuse_wT_kernel(const float* __restrict__ Whh,
                               const float* __restrict__ Wih,
                               const float* __restrict__ Who,
                               float* __restrict__ WfT)
{
    int i = blockIdx.x * 256 + threadIdx.x;    // n = i>>10 (warp-uniform), k = lane-varying
    int n = i >> 10, k = i & (HID - 1);
    double s = (double)Whh[(size_t)n * HID + k];
    #pragma unroll 8
    for (int o = 0; o < OBS; ++o)
        s += (double)Wih[n * OBS + o] * (double)Who[(size_t)o * HID + k];
    WfT[(size_t)k * HID + n] = (float)s;
}
__global__ void fuse_b1_kernel(const float* b_ih, const float* b_hh,
                               const float* Wih, const float* b_ho, float* b1)
{
    int n = blockIdx.x * 256 + threadIdx.x;
    if (n < HID) {
        double s = (double)b_ih[n] + (double)b_hh[n];
        #pragma unroll 8
        for (int o = 0; o < OBS; ++o)
            s += (double)Wih[n * OBS + o] * (double)b_ho[o];
        b1[n] = (float)s;
    }
}

// Accumulate 2 consecutive output columns (n0, n0+1) over K against the
// k-major activation tile ks[K][MS]. wt = transposed weights + n0 (row stride
// HID). Warp lanes -> 256B coalesced weight reads; LDS.128 broadcast for acts.
template<int K>
__device__ __forceinline__ void dotT(const float* __restrict__ wt,
                                     const float* __restrict__ ks,
                                     u64* __restrict__ a0, u64* __restrict__ a1)
{
    float2 cur0 = *(const float2*)(wt + 0 * HID);
    float2 cur1 = *(const float2*)(wt + 1 * HID);
    float2 cur2 = *(const float2*)(wt + 2 * HID);
    float2 cur3 = *(const float2*)(wt + 3 * HID);
    #pragma unroll 1
    for (int k = 0; k < K; k += 4) {
        int kn = (k + 4 < K) ? (k + 4) : 0;            // wrap-clamped prefetch
        float2 nx0 = *(const float2*)(wt + (kn + 0) * HID);
        float2 nx1 = *(const float2*)(wt + (kn + 1) * HID);
        float2 nx2 = *(const float2*)(wt + (kn + 2) * HID);
        float2 nx3 = *(const float2*)(wt + (kn + 3) * HID);
        #pragma unroll
        for (int kk = 0; kk < 4; ++kk) {
            float2 w = (kk == 0) ? cur0 : (kk == 1) ? cur1 : (kk == 2) ? cur2 : cur3;
            u64 d0 = dup2(w.x), d1 = dup2(w.y);
            const ulonglong2* hp = (const ulonglong2*)(ks + (k + kk) * MS);
            #pragma unroll
            for (int q = 0; q < 7; ++q) {              // 14 pairs, broadcast LDS.128
                ulonglong2 hv = hp[q];
                fma2(a0[2*q    ], hv.x, d0);
                fma2(a0[2*q + 1], hv.y, d0);
                fma2(a1[2*q    ], hv.x, d1);
                fma2(a1[2*q + 1], hv.y, d1);
            }
        }
        cur0 = nx0; cur1 = nx1; cur2 = nx2; cur3 = nx3;
    }
}

__global__ void __launch_bounds__(NT, 1)
rnn_fused_kernel(const float* __restrict__ z,
                 const float* __restrict__ b_l2h,
                 const float* __restrict__ b_ih,
                 const float* __restrict__ b_hh,
                 int T, int B)
{
    extern __shared__ float smem[];
    float* h_s = smem;                    // [HID][MS]  hidden state, k-major
    float* z_s = h_s + HID * MS;          // [LAT][MS]  z staging

    const int tid = threadIdx.x;
    const int b0r = blockIdx.x * MT;
    const int n0  = 2 * tid;              // this thread's 2 hidden columns

    for (int idx = tid; idx < MT * LAT; idx += NT) {
        int m = idx >> 7, k = idx & (LAT - 1);
        int gr = b0r + m; if (gr >= B) gr = B - 1;    // clamp ragged tail
        z_s[k * MS + m] = z[(size_t)gr * LAT + k];
    }
    __syncthreads();

    // ---- h0 = z @ W_l2h^T + b_l2h (no tanh) ----
    {
        u64 a0[NP], a1[NP];
        u64 bv0 = dup2(b_l2h[n0]), bv1 = dup2(b_l2h[n0 + 1]);
        #pragma unroll
        for (int p = 0; p < NP; ++p) { a0[p] = bv0; a1[p] = bv1; }
        dotT<LAT>(g_Wl2hT + n0, z_s, a0, a1);
        __syncthreads();
        float* r0 = h_s + n0 * MS;
        float* r1 = r0 + MS;
        #pragma unroll
        for (int p = 0; p < NP; ++p) {
            float2 v0 = unpk(a0[p]); float2 v1 = unpk(a1[p]);
            r0[2*p] = v0.x; r0[2*p + 1] = v0.y;
            r1[2*p] = v1.x; r1[2*p + 1] = v1.y;
        }
        __syncthreads();
    }

    const float bi0 = b_ih[n0] + b_hh[n0];            // t=0 bias (x0 = 0)
    const float bi1 = b_ih[n0 + 1] + b_hh[n0 + 1];
    const float bf0 = g_b1[n0];                       // fused bias (t>=1)
    const float bf1 = g_b1[n0 + 1];

    for (int t = 0; t < T; ++t) {
        u64 a0[NP], a1[NP];
        u64 bv0 = dup2((t == 0) ? bi0 : bf0);
        u64 bv1 = dup2((t == 0) ? bi1 : bf1);
        #pragma unroll
        for (int p = 0; p < NP; ++p) { a0[p] = bv0; a1[p] = bv1; }
        const float* W = (t == 0) ? g_WhhT : g_WfT;
        dotT<HID>(W + n0, h_s, a0, a1);
        __syncthreads();                  // all reads of old h done
        {
            float* r0 = h_s + n0 * MS;
            float* r1 = r0 + MS;
            float* hg = g_Hist + ((size_t)t * B + b0r) * HID + n0;
            #pragma unroll
            for (int p = 0; p < NP; ++p) {
                float2 v0 = unpk(a0[p]); float2 v1 = unpk(a1[p]);
                float t00 = tanhf(v0.x), t01 = tanhf(v0.y);   // col n0,   rows 2p,2p+1
                float t10 = tanhf(v1.x), t11 = tanhf(v1.y);   // col n0+1
                r0[2*p] = t00; r0[2*p + 1] = t01;
                r1[2*p] = t10; r1[2*p + 1] = t11;
                if (b0r + 2*p     < B) *(u64*)(hg + (size_t)(2*p)     * HID) = pk2(t00, t10);
                if (b0r + 2*p + 1 < B) *(u64*)(hg + (size_t)(2*p + 1) * HID) = pk2(t01, t11);
            }
        }
        __syncthreads();                  // new h visible
    }
}

// ---- batched projection: out[b][t][o] = Hist[t][b][:] . Who[o][:] + b_ho[o]
// (k-ascending fp32, same accumulation class as the reference projection)
#define PST 132
__global__ void __launch_bounds__(256, 2)
proj_kernel(const float* __restrict__ b_ho, float* __restrict__ out, int T, int B)
{
    __shared__ float ht[64 * PST];        // [64 k][128 m], padded rows
    const int tid = threadIdx.x;
    const int o   = tid & 63;             // output column
    const int g   = tid >> 6;             // m-group (4 x 32 rows)
    const int m0  = g * 32;
    const size_t r0 = (size_t)blockIdx.x * 128;   // rows = t*B + b

    u64 acc[16];
    u64 bv = dup2(b_ho[o]);
    #pragma unroll
    for (int p = 0; p < 16; ++p) acc[p] = bv;

    for (int kc = 0; kc < HID / 64; ++kc) {
        #pragma unroll
        for (int j = 0; j < 8; ++j) {      // stage 128x64 chunk, k-major
            int idx4 = tid + j * 256;
            int m = idx4 >> 4, k4 = (idx4 & 15) << 2;
            float4 v = *(const float4*)(g_Hist + (r0 + m) * HID + kc * 64 + k4);
            ht[(k4 + 0) * PST + m] = v.x;
            ht[(k4 + 1) * PST + m] = v.y;
            ht[(k4 + 2) * PST + m] = v.z;
            ht[(k4 + 3) * PST + m] = v.w;
        }
        __syncthreads();
        const float* wp = g_WhoT + (size_t)(kc * 64) * OBS + o;
        float wcur = wp[0];
        #pragma unroll 2
        for (int k = 0; k < 64; ++k) {
            float wnext = wp[((k + 1) & 63) * OBS];
            u64 d = dup2(wcur);
            const ulonglong2* hp = (const ulonglong2*)(ht + k * PST + m0);
            #pragma unroll
            for (int q = 0; q < 8; ++q) {  // 16 pairs, broadcast LDS.128
                ulonglong2 hv = hp[q];
                fma2(acc[2*q    ], hv.x, d);
                fma2(acc[2*q + 1], hv.y, d);
            }
            wcur = wnext;
        }
        __syncthreads();
    }

    #pragma unroll
    for (int p = 0; p < 16; ++p) {
        float2 v = unpk(acc[p]);
        size_t r = r0 + m0 + 2 * p;
        size_t t = r / (size_t)B, b = r - t * B;
        out[(b * (size_t)T + t) * OBS + o] = v.x;
        r += 1; t = r / (size_t)B; b = r - t * B;
        out[(b * (size_t)T + t) * OBS + o] = v.y;
    }
}

extern "C" void kernel_launch(void* const* d_in, const int* in_sizes, int n_in,
                              void* d_out, int out_size)
{
    const float* z     = (const float*)d_in[0];
    const float* W_l2h = (const float*)d_in[1];
    const float* b_l2h = (const float*)d_in[2];
    const float* W_ih  = (const float*)d_in[3];
    const float* b_ih  = (const float*)d_in[4];
    const float* W_hh  = (const float*)d_in[5];
    const float* b_hh  = (const float*)d_in[6];
    const float* W_ho  = (const float*)d_in[7];
    const float* b_ho  = (const float*)d_in[8];
    float* out = (float*)d_out;

    int B = in_sizes[0] / LAT;              // 4096
    int T = out_size / (B * OBS);           // 70

    float *dWfT, *dWhhT, *dWl2hT, *dWhoT, *db1;
    cudaGetSymbolAddress((void**)&dWfT,   g_WfT);
    cudaGetSymbolAddress((void**)&dWhhT,  g_WhhT);
    cudaGetSymbolAddress((void**)&dWl2hT, g_Wl2hT);
    cudaGetSymbolAddress((void**)&dWhoT,  g_WhoT);
    cudaGetSymbolAddress((void**)&db1,    g_b1);

    dim3 tb(32, 8);
    transpose_kernel<<<dim3(LAT/32, HID/32), tb>>>(W_l2h, dWl2hT, HID, LAT);
    transpose_kernel<<<dim3(HID/32, HID/32), tb>>>(W_hh,  dWhhT,  HID, HID);
    transpose_kernel<<<dim3(HID/32, OBS/32), tb>>>(W_ho,  dWhoT,  OBS, HID);
    fuse_wT_kernel<<<(HID * HID) / 256, 256>>>(W_hh, W_ih, W_ho, dWfT);
    fuse_b1_kernel<<<(HID + 255) / 256, 256>>>(b_ih, b_hh, W_ih, b_ho, db1);

    int smem_bytes = (HID * MS + LAT * MS) * (int)sizeof(float);   // 129,024 B
    cudaFuncSetAttribute(rnn_fused_kernel,
                         cudaFuncAttributeMaxDynamicSharedMemorySize, smem_bytes);

    int grid = (B + MT - 1) / MT;           // 147 CTAs, one wave
    rnn_fused_kernel<<<grid, NT, smem_bytes>>>(z, b_l2h, b_ih, b_hh, T, B);

    proj_kernel<<<(unsigned)((size_t)T * B / 128), 256>>>(b_ho, out, T, B);
}